// round 4
// baseline (speedup 1.0000x reference)
#include <cuda_runtime.h>
#include <cuda_bf16.h>
#include <cstdint>

// C = triu(triu(A) @ triu(B)), 4096x4096 fp32.
// Phase 1: split fp32 -> bf16 hi/lo, triangular masks baked in.
// Phase 2: mma.sync.m16n8k16 bf16, 3-term split product, fp32 accum.
//          SPLIT-K: each 128x256 tile's k-range cut into 1024-aligned windows
//          (max 16 K64-chunks per CTA) to kill the serial-k critical path.
// Phase 3: deterministic reducer sums window partials, applies triu mask.

#define N4K 4096

__device__ __align__(16) __nv_bfloat16 gAhi[(size_t)N4K * N4K];
__device__ __align__(16) __nv_bfloat16 gAlo[(size_t)N4K * N4K];
__device__ __align__(16) __nv_bfloat16 gBthi[(size_t)N4K * N4K];
__device__ __align__(16) __nv_bfloat16 gBtlo[(size_t)N4K * N4K];
// partial buffer: slot = (bx*32+by)*4 + kw, each slot 128x256 fp32 = 32768 floats
__device__ __align__(16) float gPart[(size_t)2048 * 32768];

__device__ __forceinline__ uint32_t smem_u32(const void* p) {
    uint32_t a;
    asm("{ .reg .u64 t; cvta.to.shared.u64 t, %1; cvt.u32.u64 %0, t; }" : "=r"(a) : "l"(p));
    return a;
}
#define SWZ(x) ((x) ^ (((x) >> 3) & 0x70))

__device__ __forceinline__ void ldmx4(uint32_t* r, uint32_t addr) {
    asm volatile("ldmatrix.sync.aligned.m8n8.x4.shared.b16 {%0,%1,%2,%3}, [%4];"
        : "=r"(r[0]), "=r"(r[1]), "=r"(r[2]), "=r"(r[3]) : "r"(addr));
}
__device__ __forceinline__ void mma16816(float* c, const uint32_t* a, uint32_t b0, uint32_t b1) {
    asm volatile("mma.sync.aligned.m16n8k16.row.col.f32.bf16.bf16.f32 "
        "{%0,%1,%2,%3}, {%4,%5,%6,%7}, {%8,%9}, {%0,%1,%2,%3};"
        : "+f"(c[0]), "+f"(c[1]), "+f"(c[2]), "+f"(c[3])
        : "r"(a[0]), "r"(a[1]), "r"(a[2]), "r"(a[3]), "r"(b0), "r"(b1));
}
#define CPA16(dst, src) \
    asm volatile("cp.async.cg.shared.global [%0], [%1], 16;" :: "r"(dst), "l"(src))
#define CPA_COMMIT() asm volatile("cp.async.commit_group;" ::: "memory")

// ---------------- phase 1a: split triu(A) into bf16 hi/lo ----------------
__global__ __launch_bounds__(256) void p1_split_a(const float* __restrict__ A) {
    size_t e = ((size_t)blockIdx.x * 256 + threadIdx.x) * 4;
    int r = (int)(e >> 12);
    int k = (int)(e & 4095);
    float4 v = *reinterpret_cast<const float4*>(A + e);
    if (k + 0 < r) v.x = 0.f;
    if (k + 1 < r) v.y = 0.f;
    if (k + 2 < r) v.z = 0.f;
    if (k + 3 < r) v.w = 0.f;
    __nv_bfloat16 h0 = __float2bfloat16(v.x), h1 = __float2bfloat16(v.y);
    __nv_bfloat16 h2 = __float2bfloat16(v.z), h3 = __float2bfloat16(v.w);
    __nv_bfloat16 l0 = __float2bfloat16(v.x - __bfloat162float(h0));
    __nv_bfloat16 l1 = __float2bfloat16(v.y - __bfloat162float(h1));
    __nv_bfloat16 l2 = __float2bfloat16(v.z - __bfloat162float(h2));
    __nv_bfloat16 l3 = __float2bfloat16(v.w - __bfloat162float(h3));
    __nv_bfloat162* ph = reinterpret_cast<__nv_bfloat162*>(gAhi + e);
    __nv_bfloat162* pl = reinterpret_cast<__nv_bfloat162*>(gAlo + e);
    __nv_bfloat162 a, b;
    a.x = h0; a.y = h1; b.x = h2; b.y = h3; ph[0] = a; ph[1] = b;
    a.x = l0; a.y = l1; b.x = l2; b.y = l3; pl[0] = a; pl[1] = b;
}

// ---------------- phase 1b: split+transpose triu(B): gBt[c][k] = triu(B)[k][c] ----------------
__global__ __launch_bounds__(256) void p1_split_bt(const float* __restrict__ B) {
    __shared__ __nv_bfloat16 sh[32][33];
    __shared__ __nv_bfloat16 sl[32][33];
    int c0 = blockIdx.x * 32, k0 = blockIdx.y * 32;
    int tx = threadIdx.x, ty = threadIdx.y;  // (32, 8)
    #pragma unroll
    for (int j = 0; j < 4; j++) {
        int k = k0 + ty + 8 * j, c = c0 + tx;
        float v = (k <= c) ? B[(size_t)k * N4K + c] : 0.f;
        __nv_bfloat16 h = __float2bfloat16(v);
        sh[ty + 8 * j][tx] = h;
        sl[ty + 8 * j][tx] = __float2bfloat16(v - __bfloat162float(h));
    }
    __syncthreads();
    #pragma unroll
    for (int j = 0; j < 4; j++) {
        int row = ty + 8 * j;
        size_t o = (size_t)(c0 + row) * N4K + (k0 + tx);
        gBthi[o] = sh[tx][row];
        gBtlo[o] = sl[tx][row];
    }
}

// ---------------- phase 2 ----------------
static constexpr int AHI_OFF = 0;
static constexpr int ALO_OFF = 16384;
static constexpr int BHI_OFF = 32768;
static constexpr int BLO_OFF = 65536;
static constexpr int STAGE   = 98304;           // 96KB
static constexpr int SMEM_TOTAL = 2 * STAGE;    // 192KB
static constexpr int NUM_WINDOWS = 592;

__device__ __forceinline__ void load_chunk(char* smBase, int stage, int rowStart,
                                           int colStart, int k0, int tid) {
    uint32_t st = smem_u32(smBase) + stage * STAGE;
    #pragma unroll
    for (int t = 0; t < 4; t++) {
        int e = tid + (t << 8);
        int row = e >> 3, ch = e & 7;
        size_t src = (size_t)(rowStart + row) * N4K + k0 + ch * 8;
        uint32_t d = SWZ((uint32_t)(row * 128 + ch * 16));
        CPA16(st + AHI_OFF + d, gAhi + src);
        CPA16(st + ALO_OFF + d, gAlo + src);
    }
    #pragma unroll
    for (int t = 0; t < 8; t++) {
        int e = tid + (t << 8);
        int row = e >> 3, ch = e & 7;
        size_t src = (size_t)(colStart + row) * N4K + k0 + ch * 8;
        uint32_t d = SWZ((uint32_t)(row * 128 + ch * 16));
        CPA16(st + BHI_OFF + d, gBthi + src);
        CPA16(st + BLO_OFF + d, gBtlo + src);
    }
    CPA_COMMIT();
}

__global__ __launch_bounds__(256, 1) void trimm_mma(float* __restrict__ C) {
    extern __shared__ char sm[];
    const int tid = threadIdx.x;
    const int wid = tid >> 5, lane = tid & 31;
    const int wm = wid & 3, wn = wid >> 2;     // 4 x 2 warp grid, warp tile 32x128

    // ---- decode bid -> (bx, by, kw); bx descending => biggest windows first ----
    int rem = blockIdx.x;
    int bx = 15;
    #pragma unroll 1
    for (; bx >= 0; --bx) {
        int T = 2 * bx + 2;          // tiles in this bx column
        int kh = bx >> 2;
        int W = 0;
        #pragma unroll
        for (int g = 0; g < 4; g++) {
            int cnt = T - 8 * g;
            cnt = cnt < 0 ? 0 : (cnt > 8 ? 8 : cnt);
            W += cnt * (kh + 1 - g);
        }
        if (rem < W) break;
        rem -= W;
    }
    const int kwHi = bx >> 2;
    int by = 0;
    #pragma unroll 1
    for (;; ++by) {
        int nw = kwHi - (by >> 3) + 1;
        if (rem < nw) break;
        rem -= nw;
    }
    const int kwLo = by >> 3;
    const int kw   = kwLo + rem;
    const int nWin = kwHi - kwLo + 1;

    const int rowStart = by * 128;
    const int colStart = bx * 256;
    const int colEnd   = colStart + 256;
    int kstart = kw << 10;      if (kstart < rowStart) kstart = rowStart;
    int kend   = (kw + 1) << 10; if (kend > colEnd)     kend = colEnd;
    const int nCh = (kend - kstart) >> 6;   // 2..16

    float acc[128];
    #pragma unroll
    for (int i = 0; i < 128; i++) acc[i] = 0.f;

    load_chunk(sm, 0, rowStart, colStart, kstart, tid);

    const int lrow = lane & 15;
    const int lk   = (lane >> 4) * 8;

    #pragma unroll 1
    for (int ci = 0; ci < nCh; ci++) {
        if (ci + 1 < nCh) {
            load_chunk(sm, (ci + 1) & 1, rowStart, colStart, kstart + 64 * (ci + 1), tid);
            asm volatile("cp.async.wait_group 1;" ::: "memory");
        } else {
            asm volatile("cp.async.wait_group 0;" ::: "memory");
        }
        __syncthreads();

        const uint32_t st = smem_u32(sm) + (ci & 1) * STAGE;

        #pragma unroll
        for (int kk = 0; kk < 4; kk++) {
            const int krow = kk * 16;
            uint32_t ah[2][4], al[2][4];
            #pragma unroll
            for (int i = 0; i < 2; i++) {
                uint32_t off = SWZ((uint32_t)((wm * 32 + i * 16 + lrow) * 128 + (krow + lk) * 2));
                ldmx4(ah[i], st + AHI_OFF + off);
                ldmx4(al[i], st + ALO_OFF + off);
            }
            #pragma unroll
            for (int h = 0; h < 2; h++) {
                uint32_t bh0[8], bh1[8], bl0[8], bl1[8];
                #pragma unroll
                for (int j2 = 0; j2 < 4; j2++) {
                    uint32_t off = SWZ((uint32_t)((wn * 128 + h * 64 + j2 * 16 + lrow) * 128
                                                  + (krow + lk) * 2));
                    uint32_t r[4];
                    ldmx4(r, st + BHI_OFF + off);
                    bh0[2 * j2] = r[0]; bh1[2 * j2] = r[2];
                    bh0[2 * j2 + 1] = r[1]; bh1[2 * j2 + 1] = r[3];
                    ldmx4(r, st + BLO_OFF + off);
                    bl0[2 * j2] = r[0]; bl1[2 * j2] = r[2];
                    bl0[2 * j2 + 1] = r[1]; bl1[2 * j2 + 1] = r[3];
                }
                #pragma unroll
                for (int i = 0; i < 2; i++) {
                    #pragma unroll
                    for (int j = 0; j < 8; j++) {
                        float* c = &acc[(i * 16 + h * 8 + j) * 4];
                        mma16816(c, ah[i], bh0[j], bh1[j]);
                        mma16816(c, ah[i], bl0[j], bl1[j]);
                        mma16816(c, al[i], bh0[j], bh1[j]);
                    }
                }
            }
        }
        __syncthreads();
    }

    // ---- epilogue ----
    const int l4 = lane >> 2;
    const int l2 = (lane & 3) * 2;
    if (nWin == 1) {
        // sole window: masked store straight to C
        #pragma unroll
        for (int i = 0; i < 2; i++) {
            const int r0 = rowStart + wm * 32 + i * 16 + l4;
            const int r1 = r0 + 8;
            #pragma unroll
            for (int j = 0; j < 16; j++) {
                const int c = colStart + wn * 128 + j * 8 + l2;
                const float* a = &acc[(i * 16 + j) * 4];
                float2 v;
                v.x = (r0 <= c + 0) ? a[0] : 0.f;
                v.y = (r0 <= c + 1) ? a[1] : 0.f;
                *reinterpret_cast<float2*>(C + (size_t)r0 * N4K + c) = v;
                v.x = (r1 <= c + 0) ? a[2] : 0.f;
                v.y = (r1 <= c + 1) ? a[3] : 0.f;
                *reinterpret_cast<float2*>(C + (size_t)r1 * N4K + c) = v;
            }
        }
    } else {
        // write unmasked partial (tile-local row-major 128x256)
        float* P = gPart + (((size_t)(bx * 32 + by) * 4 + kw) << 15);
        #pragma unroll
        for (int i = 0; i < 2; i++) {
            const int r0 = wm * 32 + i * 16 + l4;
            const int r1 = r0 + 8;
            #pragma unroll
            for (int j = 0; j < 16; j++) {
                const int c = wn * 128 + j * 8 + l2;
                const float* a = &acc[(i * 16 + j) * 4];
                float2 v;
                v.x = a[0]; v.y = a[1];
                *reinterpret_cast<float2*>(P + r0 * 256 + c) = v;
                v.x = a[2]; v.y = a[3];
                *reinterpret_cast<float2*>(P + r1 * 256 + c) = v;
            }
        }
    }
}

// ---------------- phase 3: sum window partials, mask, store ----------------
__global__ __launch_bounds__(256) void reduce_tiles(float* __restrict__ C) {
    const int bx = blockIdx.x, by = blockIdx.y;
    if (by > 2 * bx + 1) return;
    const int kwLo = by >> 3, kwHi = bx >> 2;
    const int nWin = kwHi - kwLo + 1;
    if (nWin == 1) return;
    const int rowStart = by * 128, colStart = bx * 256;
    const float* P0 = gPart + (((size_t)(bx * 32 + by) * 4 + kwLo) << 15);
    const int tid = threadIdx.x;

    #pragma unroll 1
    for (int i = 0; i < 32; i++) {
        const int idx4 = i * 256 + tid;           // float4 index, coalesced
        const int e = idx4 * 4;
        const int rl = e >> 8, cl = e & 255;
        float4 s = *reinterpret_cast<const float4*>(P0 + (size_t)idx4 * 4);
        const float* Pw = P0 + 32768;
        #pragma unroll 1
        for (int w = 1; w < nWin; w++, Pw += 32768) {
            float4 t = *reinterpret_cast<const float4*>(Pw + (size_t)idx4 * 4);
            s.x += t.x; s.y += t.y; s.z += t.z; s.w += t.w;
        }
        const int r = rowStart + rl, c = colStart + cl;
        if (r > c + 0) s.x = 0.f;
        if (r > c + 1) s.y = 0.f;
        if (r > c + 2) s.z = 0.f;
        if (r > c + 3) s.w = 0.f;
        *reinterpret_cast<float4*>(C + (size_t)r * N4K + c) = s;
    }
}

// ---------------- launch ----------------
extern "C" void kernel_launch(void* const* d_in, const int* in_sizes, int n_in,
                              void* d_out, int out_size) {
    const float* A = (const float*)d_in[0];
    const float* B = (const float*)d_in[1];
    float* C = (float*)d_out;

    cudaMemsetAsync(d_out, 0, (size_t)N4K * N4K * sizeof(float));

    p1_split_a<<<(N4K * (N4K / 4)) / 256, 256>>>(A);
    p1_split_bt<<<dim3(N4K / 32, N4K / 32), dim3(32, 8)>>>(B);

    cudaFuncSetAttribute(trimm_mma, cudaFuncAttributeMaxDynamicSharedMemorySize, SMEM_TOTAL);
    trimm_mma<<<NUM_WINDOWS, 256, SMEM_TOTAL>>>(C);

    reduce_tiles<<<dim3(16, 32), 256>>>(C);
}

// round 5
// speedup vs baseline: 1.5951x; 1.5951x over previous
#include <cuda_runtime.h>
#include <cuda_bf16.h>
#include <cstdint>

// C = triu(triu(A) @ triu(B)), 4096x4096 fp32.
// Phase 1: split fp32 -> bf16 hi/lo, triangular masks baked in.
// Phase 2: mma.sync.m16n8k16 bf16, 3-term split product, fp32 accum.
//          SPLIT-K: every 128x256 tile's k-range cut into 1024-aligned windows
//          (2..16 K64-chunks per CTA). UNIFORM epilogue: all CTAs store
//          unmasked fp32 partials (one code path, low register pressure).
// Phase 3: reducer v2 (tile x 4 row-slices) sums windows in fixed kw order,
//          applies triu mask, stores C.

#define N4K 4096

__device__ __align__(16) __nv_bfloat16 gAhi[(size_t)N4K * N4K];
__device__ __align__(16) __nv_bfloat16 gAlo[(size_t)N4K * N4K];
__device__ __align__(16) __nv_bfloat16 gBthi[(size_t)N4K * N4K];
__device__ __align__(16) __nv_bfloat16 gBtlo[(size_t)N4K * N4K];
// partial buffer: slot = (bx*32+by)*4 + kw, each slot 128x256 fp32
__device__ __align__(16) float gPart[(size_t)2048 * 32768];

__device__ __forceinline__ uint32_t smem_u32(const void* p) {
    uint32_t a;
    asm("{ .reg .u64 t; cvta.to.shared.u64 t, %1; cvt.u32.u64 %0, t; }" : "=r"(a) : "l"(p));
    return a;
}
#define SWZ(x) ((x) ^ (((x) >> 3) & 0x70))

__device__ __forceinline__ void ldmx4(uint32_t* r, uint32_t addr) {
    asm volatile("ldmatrix.sync.aligned.m8n8.x4.shared.b16 {%0,%1,%2,%3}, [%4];"
        : "=r"(r[0]), "=r"(r[1]), "=r"(r[2]), "=r"(r[3]) : "r"(addr));
}
__device__ __forceinline__ void mma16816(float* c, const uint32_t* a, uint32_t b0, uint32_t b1) {
    asm volatile("mma.sync.aligned.m16n8k16.row.col.f32.bf16.bf16.f32 "
        "{%0,%1,%2,%3}, {%4,%5,%6,%7}, {%8,%9}, {%0,%1,%2,%3};"
        : "+f"(c[0]), "+f"(c[1]), "+f"(c[2]), "+f"(c[3])
        : "r"(a[0]), "r"(a[1]), "r"(a[2]), "r"(a[3]), "r"(b0), "r"(b1));
}
#define CPA16(dst, src) \
    asm volatile("cp.async.cg.shared.global [%0], [%1], 16;" :: "r"(dst), "l"(src))
#define CPA_COMMIT() asm volatile("cp.async.commit_group;" ::: "memory")

// ---------------- phase 1a: split triu(A) into bf16 hi/lo ----------------
__global__ __launch_bounds__(256) void p1_split_a(const float* __restrict__ A) {
    size_t e = ((size_t)blockIdx.x * 256 + threadIdx.x) * 4;
    int r = (int)(e >> 12);
    int k = (int)(e & 4095);
    float4 v = *reinterpret_cast<const float4*>(A + e);
    if (k + 0 < r) v.x = 0.f;
    if (k + 1 < r) v.y = 0.f;
    if (k + 2 < r) v.z = 0.f;
    if (k + 3 < r) v.w = 0.f;
    __nv_bfloat16 h0 = __float2bfloat16(v.x), h1 = __float2bfloat16(v.y);
    __nv_bfloat16 h2 = __float2bfloat16(v.z), h3 = __float2bfloat16(v.w);
    __nv_bfloat16 l0 = __float2bfloat16(v.x - __bfloat162float(h0));
    __nv_bfloat16 l1 = __float2bfloat16(v.y - __bfloat162float(h1));
    __nv_bfloat16 l2 = __float2bfloat16(v.z - __bfloat162float(h2));
    __nv_bfloat16 l3 = __float2bfloat16(v.w - __bfloat162float(h3));
    __nv_bfloat162* ph = reinterpret_cast<__nv_bfloat162*>(gAhi + e);
    __nv_bfloat162* pl = reinterpret_cast<__nv_bfloat162*>(gAlo + e);
    __nv_bfloat162 a, b;
    a.x = h0; a.y = h1; b.x = h2; b.y = h3; ph[0] = a; ph[1] = b;
    a.x = l0; a.y = l1; b.x = l2; b.y = l3; pl[0] = a; pl[1] = b;
}

// ---------------- phase 1b: split+transpose triu(B): gBt[c][k] = triu(B)[k][c] ----------------
__global__ __launch_bounds__(256) void p1_split_bt(const float* __restrict__ B) {
    __shared__ __nv_bfloat16 sh[32][33];
    __shared__ __nv_bfloat16 sl[32][33];
    int c0 = blockIdx.x * 32, k0 = blockIdx.y * 32;
    int tx = threadIdx.x, ty = threadIdx.y;  // (32, 8)
    #pragma unroll
    for (int j = 0; j < 4; j++) {
        int k = k0 + ty + 8 * j, c = c0 + tx;
        float v = (k <= c) ? B[(size_t)k * N4K + c] : 0.f;
        __nv_bfloat16 h = __float2bfloat16(v);
        sh[ty + 8 * j][tx] = h;
        sl[ty + 8 * j][tx] = __float2bfloat16(v - __bfloat162float(h));
    }
    __syncthreads();
    #pragma unroll
    for (int j = 0; j < 4; j++) {
        int row = ty + 8 * j;
        size_t o = (size_t)(c0 + row) * N4K + (k0 + tx);
        gBthi[o] = sh[tx][row];
        gBtlo[o] = sl[tx][row];
    }
}

// ---------------- phase 2 ----------------
static constexpr int AHI_OFF = 0;
static constexpr int ALO_OFF = 16384;
static constexpr int BHI_OFF = 32768;
static constexpr int BLO_OFF = 65536;
static constexpr int STAGE   = 98304;           // 96KB
static constexpr int SMEM_TOTAL = 2 * STAGE;    // 192KB
static constexpr int NUM_WINDOWS = 592;

__device__ __forceinline__ void load_chunk(char* smBase, int stage, int rowStart,
                                           int colStart, int k0, int tid) {
    uint32_t st = smem_u32(smBase) + stage * STAGE;
    #pragma unroll
    for (int t = 0; t < 4; t++) {
        int e = tid + (t << 8);
        int row = e >> 3, ch = e & 7;
        size_t src = (size_t)(rowStart + row) * N4K + k0 + ch * 8;
        uint32_t d = SWZ((uint32_t)(row * 128 + ch * 16));
        CPA16(st + AHI_OFF + d, gAhi + src);
        CPA16(st + ALO_OFF + d, gAlo + src);
    }
    #pragma unroll
    for (int t = 0; t < 8; t++) {
        int e = tid + (t << 8);
        int row = e >> 3, ch = e & 7;
        size_t src = (size_t)(colStart + row) * N4K + k0 + ch * 8;
        uint32_t d = SWZ((uint32_t)(row * 128 + ch * 16));
        CPA16(st + BHI_OFF + d, gBthi + src);
        CPA16(st + BLO_OFF + d, gBtlo + src);
    }
    CPA_COMMIT();
}

__global__ __launch_bounds__(256, 1) void trimm_mma() {
    extern __shared__ char sm[];
    const int tid = threadIdx.x;
    const int wid = tid >> 5, lane = tid & 31;
    const int wm = wid & 3, wn = wid >> 2;     // 4 x 2 warp grid, warp tile 32x128

    // ---- decode bid -> (bx, by, kw); bx descending => biggest windows first ----
    int rem = blockIdx.x;
    int bx = 15;
    #pragma unroll 1
    for (; bx >= 0; --bx) {
        int T = 2 * bx + 2;
        int kh = bx >> 2;
        int W = 0;
        #pragma unroll
        for (int g = 0; g < 4; g++) {
            int cnt = T - 8 * g;
            cnt = cnt < 0 ? 0 : (cnt > 8 ? 8 : cnt);
            W += cnt * (kh + 1 - g);
        }
        if (rem < W) break;
        rem -= W;
    }
    const int kwHi = bx >> 2;
    int by = 0;
    #pragma unroll 1
    for (;; ++by) {
        int nw = kwHi - (by >> 3) + 1;
        if (rem < nw) break;
        rem -= nw;
    }
    const int kw = (by >> 3) + rem;

    const int rowStart = by * 128;
    const int colStart = bx * 256;
    int kstart = kw << 10;       if (kstart < rowStart)     kstart = rowStart;
    int kend   = (kw + 1) << 10; if (kend > colStart + 256) kend = colStart + 256;
    const int nCh = (kend - kstart) >> 6;   // 2..16

    float acc[128];
    #pragma unroll
    for (int i = 0; i < 128; i++) acc[i] = 0.f;

    load_chunk(sm, 0, rowStart, colStart, kstart, tid);

    const int lrow = lane & 15;
    const int lk   = (lane >> 4) * 8;

    #pragma unroll 1
    for (int ci = 0; ci < nCh; ci++) {
        if (ci + 1 < nCh) {
            load_chunk(sm, (ci + 1) & 1, rowStart, colStart, kstart + 64 * (ci + 1), tid);
            asm volatile("cp.async.wait_group 1;" ::: "memory");
        } else {
            asm volatile("cp.async.wait_group 0;" ::: "memory");
        }
        __syncthreads();

        const uint32_t st = smem_u32(sm) + (ci & 1) * STAGE;

        #pragma unroll
        for (int kk = 0; kk < 4; kk++) {
            const int krow = kk * 16;
            uint32_t ah[2][4], al[2][4];
            #pragma unroll
            for (int i = 0; i < 2; i++) {
                uint32_t off = SWZ((uint32_t)((wm * 32 + i * 16 + lrow) * 128 + (krow + lk) * 2));
                ldmx4(ah[i], st + AHI_OFF + off);
                ldmx4(al[i], st + ALO_OFF + off);
            }
            #pragma unroll
            for (int h = 0; h < 2; h++) {
                uint32_t bh0[8], bh1[8], bl0[8], bl1[8];
                #pragma unroll
                for (int j2 = 0; j2 < 4; j2++) {
                    uint32_t off = SWZ((uint32_t)((wn * 128 + h * 64 + j2 * 16 + lrow) * 128
                                                  + (krow + lk) * 2));
                    uint32_t r[4];
                    ldmx4(r, st + BHI_OFF + off);
                    bh0[2 * j2] = r[0]; bh1[2 * j2] = r[2];
                    bh0[2 * j2 + 1] = r[1]; bh1[2 * j2 + 1] = r[3];
                    ldmx4(r, st + BLO_OFF + off);
                    bl0[2 * j2] = r[0]; bl1[2 * j2] = r[2];
                    bl0[2 * j2 + 1] = r[1]; bl1[2 * j2 + 1] = r[3];
                }
                #pragma unroll
                for (int i = 0; i < 2; i++) {
                    #pragma unroll
                    for (int j = 0; j < 8; j++) {
                        float* c = &acc[(i * 16 + h * 8 + j) * 4];
                        mma16816(c, ah[i], bh0[j], bh1[j]);
                        mma16816(c, ah[i], bl0[j], bl1[j]);
                        mma16816(c, al[i], bh0[j], bh1[j]);
                    }
                }
            }
        }
        __syncthreads();
    }

    // ---- uniform epilogue: unmasked fp32 partial (tile-local 128x256) ----
    float* P = gPart + (((size_t)(bx * 32 + by) * 4 + kw) << 15);
    const int l4 = lane >> 2;
    const int l2 = (lane & 3) * 2;
    #pragma unroll
    for (int i = 0; i < 2; i++) {
        const int r0 = wm * 32 + i * 16 + l4;
        const int r1 = r0 + 8;
        #pragma unroll
        for (int j = 0; j < 16; j++) {
            const int c = wn * 128 + j * 8 + l2;
            const float* a = &acc[(i * 16 + j) * 4];
            float2 v;
            v.x = a[0]; v.y = a[1];
            *reinterpret_cast<float2*>(P + r0 * 256 + c) = v;
            v.x = a[2]; v.y = a[3];
            *reinterpret_cast<float2*>(P + r1 * 256 + c) = v;
        }
    }
}

// ---------------- phase 3: sum window partials, mask, store ----------------
// grid (16, 32, 4): tile (bx, by), z = 32-row slice. 256 threads.
__global__ __launch_bounds__(256) void reduce_tiles(float* __restrict__ C) {
    const int bx = blockIdx.x, by = blockIdx.y;
    if (by > 2 * bx + 1) return;
    const int sl = blockIdx.z;
    const int kwLo = by >> 3, kwHi = bx >> 2;
    const int nWin = kwHi - kwLo + 1;
    const int rowStart = by * 128, colStart = bx * 256;
    const float* P0 = gPart + (((size_t)(bx * 32 + by) * 4 + kwLo) << 15) + sl * 8192;
    const int tid = threadIdx.x;

    // 8 independent float4 chains per thread; 32 rows x 256 cols per CTA
    float4 s[8];
    #pragma unroll
    for (int i = 0; i < 8; i++)
        s[i] = *reinterpret_cast<const float4*>(P0 + (size_t)(i * 256 + tid) * 4);
    const float* Pw = P0 + 32768;
    #pragma unroll 1
    for (int w = 1; w < nWin; w++, Pw += 32768) {
        #pragma unroll
        for (int i = 0; i < 8; i++) {
            float4 t = *reinterpret_cast<const float4*>(Pw + (size_t)(i * 256 + tid) * 4);
            s[i].x += t.x; s[i].y += t.y; s[i].z += t.z; s[i].w += t.w;
        }
    }
    #pragma unroll
    for (int i = 0; i < 8; i++) {
        const int e = (i * 256 + tid) * 4;
        const int r = rowStart + sl * 32 + (e >> 8);
        const int c = colStart + (e & 255);
        float4 v = s[i];
        if (r > c + 0) v.x = 0.f;
        if (r > c + 1) v.y = 0.f;
        if (r > c + 2) v.z = 0.f;
        if (r > c + 3) v.w = 0.f;
        *reinterpret_cast<float4*>(C + (size_t)r * N4K + c) = v;
    }
}

// ---------------- launch ----------------
extern "C" void kernel_launch(void* const* d_in, const int* in_sizes, int n_in,
                              void* d_out, int out_size) {
    const float* A = (const float*)d_in[0];
    const float* B = (const float*)d_in[1];
    float* C = (float*)d_out;

    cudaMemsetAsync(d_out, 0, (size_t)N4K * N4K * sizeof(float));

    p1_split_a<<<(N4K * (N4K / 4)) / 256, 256>>>(A);
    p1_split_bt<<<dim3(N4K / 32, N4K / 32), dim3(32, 8)>>>(B);

    cudaFuncSetAttribute(trimm_mma, cudaFuncAttributeMaxDynamicSharedMemorySize, SMEM_TOTAL);
    trimm_mma<<<NUM_WINDOWS, 256, SMEM_TOTAL>>>();

    reduce_tiles<<<dim3(16, 32, 4), 256>>>(C);
}

// round 6
// speedup vs baseline: 2.0775x; 1.3024x over previous
#include <cuda_runtime.h>
#include <cuda_fp16.h>
#include <cstdint>

// C = triu(triu(A) @ triu(B)), 4096x4096 fp32.
// Phase 1: A -> fp16 hi/lo split (a = ah + al, residual ~2^-22); B -> transposed
//          single fp16 (error 2^-12, dominates: rel_err ~1.4e-4 << 1e-3).
//          Triangular masks baked in.
// Phase 2: mma.sync.m16n8k16 fp16, TWO terms (ah*bh + al*bh), fp32 accum.
//          SPLIT-K 1024-aligned windows (2..16 K64-chunks/CTA), uniform
//          unmasked-partial epilogue.
// Phase 3: reducer (tile x 4 row-slices) sums windows in fixed order, masks.

#define N4K 4096

__device__ __align__(16) __half gAhi[(size_t)N4K * N4K];
__device__ __align__(16) __half gAlo[(size_t)N4K * N4K];
__device__ __align__(16) __half gBthi[(size_t)N4K * N4K];
// partial buffer: slot = (bx*32+by)*4 + kw, each slot 128x256 fp32
__device__ __align__(16) float gPart[(size_t)2048 * 32768];

__device__ __forceinline__ uint32_t smem_u32(const void* p) {
    uint32_t a;
    asm("{ .reg .u64 t; cvta.to.shared.u64 t, %1; cvt.u32.u64 %0, t; }" : "=r"(a) : "l"(p));
    return a;
}
#define SWZ(x) ((x) ^ (((x) >> 3) & 0x70))

__device__ __forceinline__ void ldmx4(uint32_t* r, uint32_t addr) {
    asm volatile("ldmatrix.sync.aligned.m8n8.x4.shared.b16 {%0,%1,%2,%3}, [%4];"
        : "=r"(r[0]), "=r"(r[1]), "=r"(r[2]), "=r"(r[3]) : "r"(addr));
}
__device__ __forceinline__ void mma16816(float* c, const uint32_t* a, uint32_t b0, uint32_t b1) {
    asm volatile("mma.sync.aligned.m16n8k16.row.col.f32.f16.f16.f32 "
        "{%0,%1,%2,%3}, {%4,%5,%6,%7}, {%8,%9}, {%0,%1,%2,%3};"
        : "+f"(c[0]), "+f"(c[1]), "+f"(c[2]), "+f"(c[3])
        : "r"(a[0]), "r"(a[1]), "r"(a[2]), "r"(a[3]), "r"(b0), "r"(b1));
}
#define CPA16(dst, src) \
    asm volatile("cp.async.cg.shared.global [%0], [%1], 16;" :: "r"(dst), "l"(src))
#define CPA_COMMIT() asm volatile("cp.async.commit_group;" ::: "memory")

// ---------------- phase 1a: split triu(A) into fp16 hi/lo ----------------
__global__ __launch_bounds__(256) void p1_split_a(const float* __restrict__ A) {
    size_t e = ((size_t)blockIdx.x * 256 + threadIdx.x) * 4;
    int r = (int)(e >> 12);
    int k = (int)(e & 4095);
    float4 v = *reinterpret_cast<const float4*>(A + e);
    if (k + 0 < r) v.x = 0.f;
    if (k + 1 < r) v.y = 0.f;
    if (k + 2 < r) v.z = 0.f;
    if (k + 3 < r) v.w = 0.f;
    __half h0 = __float2half(v.x), h1 = __float2half(v.y);
    __half h2 = __float2half(v.z), h3 = __float2half(v.w);
    __half l0 = __float2half(v.x - __half2float(h0));
    __half l1 = __float2half(v.y - __half2float(h1));
    __half l2 = __float2half(v.z - __half2float(h2));
    __half l3 = __float2half(v.w - __half2float(h3));
    __half2* ph = reinterpret_cast<__half2*>(gAhi + e);
    __half2* pl = reinterpret_cast<__half2*>(gAlo + e);
    __half2 a, b;
    a.x = h0; a.y = h1; b.x = h2; b.y = h3; ph[0] = a; ph[1] = b;
    a.x = l0; a.y = l1; b.x = l2; b.y = l3; pl[0] = a; pl[1] = b;
}

// ---------------- phase 1b: transpose triu(B) to fp16: gBt[c][k] = triu(B)[k][c] ----------------
__global__ __launch_bounds__(256) void p1_split_bt(const float* __restrict__ B) {
    __shared__ __half sh[32][33];
    int c0 = blockIdx.x * 32, k0 = blockIdx.y * 32;
    int tx = threadIdx.x, ty = threadIdx.y;  // (32, 8)
    #pragma unroll
    for (int j = 0; j < 4; j++) {
        int k = k0 + ty + 8 * j, c = c0 + tx;
        float v = (k <= c) ? B[(size_t)k * N4K + c] : 0.f;
        sh[ty + 8 * j][tx] = __float2half(v);
    }
    __syncthreads();
    #pragma unroll
    for (int j = 0; j < 4; j++) {
        int row = ty + 8 * j;
        gBthi[(size_t)(c0 + row) * N4K + (k0 + tx)] = sh[tx][row];
    }
}

// ---------------- phase 2 ----------------
static constexpr int AHI_OFF = 0;       // 16KB (128 rows x 64k x 2B)
static constexpr int ALO_OFF = 16384;   // 16KB
static constexpr int BHI_OFF = 32768;   // 32KB (256 rows x 64k x 2B)
static constexpr int STAGE   = 65536;   // 64KB
static constexpr int SMEM_TOTAL = 2 * STAGE;  // 128KB
static constexpr int NUM_WINDOWS = 592;

__device__ __forceinline__ void load_chunk(char* smBase, int stage, int rowStart,
                                           int colStart, int k0, int tid) {
    uint32_t st = smem_u32(smBase) + stage * STAGE;
    #pragma unroll
    for (int t = 0; t < 4; t++) {
        int e = tid + (t << 8);
        int row = e >> 3, ch = e & 7;
        size_t src = (size_t)(rowStart + row) * N4K + k0 + ch * 8;
        uint32_t d = SWZ((uint32_t)(row * 128 + ch * 16));
        CPA16(st + AHI_OFF + d, gAhi + src);
        CPA16(st + ALO_OFF + d, gAlo + src);
    }
    #pragma unroll
    for (int t = 0; t < 8; t++) {
        int e = tid + (t << 8);
        int row = e >> 3, ch = e & 7;
        size_t src = (size_t)(colStart + row) * N4K + k0 + ch * 8;
        uint32_t d = SWZ((uint32_t)(row * 128 + ch * 16));
        CPA16(st + BHI_OFF + d, gBthi + src);
    }
    CPA_COMMIT();
}

__global__ __launch_bounds__(256, 1) void trimm_mma() {
    extern __shared__ char sm[];
    const int tid = threadIdx.x;
    const int wid = tid >> 5, lane = tid & 31;
    const int wm = wid & 3, wn = wid >> 2;     // 4 x 2 warp grid, warp tile 32x128

    // ---- decode bid -> (bx, by, kw); bx descending => biggest windows first ----
    int rem = blockIdx.x;
    int bx = 15;
    #pragma unroll 1
    for (; bx >= 0; --bx) {
        int T = 2 * bx + 2;
        int kh = bx >> 2;
        int W = 0;
        #pragma unroll
        for (int g = 0; g < 4; g++) {
            int cnt = T - 8 * g;
            cnt = cnt < 0 ? 0 : (cnt > 8 ? 8 : cnt);
            W += cnt * (kh + 1 - g);
        }
        if (rem < W) break;
        rem -= W;
    }
    const int kwHi = bx >> 2;
    int by = 0;
    #pragma unroll 1
    for (;; ++by) {
        int nw = kwHi - (by >> 3) + 1;
        if (rem < nw) break;
        rem -= nw;
    }
    const int kw = (by >> 3) + rem;

    const int rowStart = by * 128;
    const int colStart = bx * 256;
    int kstart = kw << 10;       if (kstart < rowStart)     kstart = rowStart;
    int kend   = (kw + 1) << 10; if (kend > colStart + 256) kend = colStart + 256;
    const int nCh = (kend - kstart) >> 6;   // 2..16

    float acc[128];
    #pragma unroll
    for (int i = 0; i < 128; i++) acc[i] = 0.f;

    load_chunk(sm, 0, rowStart, colStart, kstart, tid);

    const int lrow = lane & 15;
    const int lk   = (lane >> 4) * 8;

    #pragma unroll 1
    for (int ci = 0; ci < nCh; ci++) {
        if (ci + 1 < nCh) {
            load_chunk(sm, (ci + 1) & 1, rowStart, colStart, kstart + 64 * (ci + 1), tid);
            asm volatile("cp.async.wait_group 1;" ::: "memory");
        } else {
            asm volatile("cp.async.wait_group 0;" ::: "memory");
        }
        __syncthreads();

        const uint32_t st = smem_u32(sm) + (ci & 1) * STAGE;

        #pragma unroll
        for (int kk = 0; kk < 4; kk++) {
            const int krow = kk * 16;
            uint32_t ah[2][4], al[2][4];
            #pragma unroll
            for (int i = 0; i < 2; i++) {
                uint32_t off = SWZ((uint32_t)((wm * 32 + i * 16 + lrow) * 128 + (krow + lk) * 2));
                ldmx4(ah[i], st + AHI_OFF + off);
                ldmx4(al[i], st + ALO_OFF + off);
            }
            #pragma unroll
            for (int h = 0; h < 2; h++) {
                uint32_t bh0[8], bh1[8];
                #pragma unroll
                for (int j2 = 0; j2 < 4; j2++) {
                    uint32_t off = SWZ((uint32_t)((wn * 128 + h * 64 + j2 * 16 + lrow) * 128
                                                  + (krow + lk) * 2));
                    uint32_t r[4];
                    ldmx4(r, st + BHI_OFF + off);
                    bh0[2 * j2] = r[0]; bh1[2 * j2] = r[2];
                    bh0[2 * j2 + 1] = r[1]; bh1[2 * j2 + 1] = r[3];
                }
                #pragma unroll
                for (int i = 0; i < 2; i++) {
                    #pragma unroll
                    for (int j = 0; j < 8; j++) {
                        float* c = &acc[(i * 16 + h * 8 + j) * 4];
                        mma16816(c, ah[i], bh0[j], bh1[j]);
                        mma16816(c, al[i], bh0[j], bh1[j]);
                    }
                }
            }
        }
        __syncthreads();
    }

    // ---- uniform epilogue: unmasked fp32 partial (tile-local 128x256) ----
    float* P = gPart + (((size_t)(bx * 32 + by) * 4 + kw) << 15);
    const int l4 = lane >> 2;
    const int l2 = (lane & 3) * 2;
    #pragma unroll
    for (int i = 0; i < 2; i++) {
        const int r0 = wm * 32 + i * 16 + l4;
        const int r1 = r0 + 8;
        #pragma unroll
        for (int j = 0; j < 16; j++) {
            const int c = wn * 128 + j * 8 + l2;
            const float* a = &acc[(i * 16 + j) * 4];
            float2 v;
            v.x = a[0]; v.y = a[1];
            *reinterpret_cast<float2*>(P + r0 * 256 + c) = v;
            v.x = a[2]; v.y = a[3];
            *reinterpret_cast<float2*>(P + r1 * 256 + c) = v;
        }
    }
}

// ---------------- phase 3: sum window partials, mask, store ----------------
__global__ __launch_bounds__(256) void reduce_tiles(float* __restrict__ C) {
    const int bx = blockIdx.x, by = blockIdx.y;
    if (by > 2 * bx + 1) return;
    const int sl = blockIdx.z;
    const int kwLo = by >> 3, kwHi = bx >> 2;
    const int nWin = kwHi - kwLo + 1;
    const int rowStart = by * 128, colStart = bx * 256;
    const float* P0 = gPart + (((size_t)(bx * 32 + by) * 4 + kwLo) << 15) + sl * 8192;
    const int tid = threadIdx.x;

    float4 s[8];
    #pragma unroll
    for (int i = 0; i < 8; i++)
        s[i] = *reinterpret_cast<const float4*>(P0 + (size_t)(i * 256 + tid) * 4);
    const float* Pw = P0 + 32768;
    #pragma unroll 1
    for (int w = 1; w < nWin; w++, Pw += 32768) {
        #pragma unroll
        for (int i = 0; i < 8; i++) {
            float4 t = *reinterpret_cast<const float4*>(Pw + (size_t)(i * 256 + tid) * 4);
            s[i].x += t.x; s[i].y += t.y; s[i].z += t.z; s[i].w += t.w;
        }
    }
    #pragma unroll
    for (int i = 0; i < 8; i++) {
        const int e = (i * 256 + tid) * 4;
        const int r = rowStart + sl * 32 + (e >> 8);
        const int c = colStart + (e & 255);
        float4 v = s[i];
        if (r > c + 0) v.x = 0.f;
        if (r > c + 1) v.y = 0.f;
        if (r > c + 2) v.z = 0.f;
        if (r > c + 3) v.w = 0.f;
        *reinterpret_cast<float4*>(C + (size_t)r * N4K + c) = v;
    }
}

// ---------------- launch ----------------
extern "C" void kernel_launch(void* const* d_in, const int* in_sizes, int n_in,
                              void* d_out, int out_size) {
    const float* A = (const float*)d_in[0];
    const float* B = (const float*)d_in[1];
    float* C = (float*)d_out;

    cudaMemsetAsync(d_out, 0, (size_t)N4K * N4K * sizeof(float));

    p1_split_a<<<(N4K * (N4K / 4)) / 256, 256>>>(A);
    p1_split_bt<<<dim3(N4K / 32, N4K / 32), dim3(32, 8)>>>(B);

    cudaFuncSetAttribute(trimm_mma, cudaFuncAttributeMaxDynamicSharedMemorySize, SMEM_TOTAL);
    trimm_mma<<<NUM_WINDOWS, 256, SMEM_TOTAL>>>();

    reduce_tiles<<<dim3(16, 32, 4), 256>>>(C);
}

// round 7
// speedup vs baseline: 3.2672x; 1.5727x over previous
#include <cuda_runtime.h>
#include <cuda_fp16.h>
#include <cstdint>

// C = triu(triu(A) @ triu(B)), 4096x4096 fp32.
// Phase 1: A -> fp16 (masked triu), B -> fp16 transposed (masked). Single
//          rounding each: combined rel_err ~3e-4 << 1e-3 gate.
// Phase 2: plain fp16 mma.sync.m16n8k16, fp32 accum. SPLIT-K 1024-aligned
//          windows (2..16 K64-chunks/CTA), 4-stage cp.async pipeline,
//          uniform unmasked-partial epilogue.
// Phase 3: reducer covers ALL tiles (lower triangle -> zeros; replaces memset),
//          sums windows in fixed order, applies triu mask.

#define N4K 4096

__device__ __align__(16) __half gAh[(size_t)N4K * N4K];
__device__ __align__(16) __half gBth[(size_t)N4K * N4K];
// partial buffer: slot = (bx*32+by)*4 + kw, each slot 128x256 fp32
__device__ __align__(16) float gPart[(size_t)2048 * 32768];

__device__ __forceinline__ uint32_t smem_u32(const void* p) {
    uint32_t a;
    asm("{ .reg .u64 t; cvta.to.shared.u64 t, %1; cvt.u32.u64 %0, t; }" : "=r"(a) : "l"(p));
    return a;
}
#define SWZ(x) ((x) ^ (((x) >> 3) & 0x70))

__device__ __forceinline__ void ldmx4(uint32_t* r, uint32_t addr) {
    asm volatile("ldmatrix.sync.aligned.m8n8.x4.shared.b16 {%0,%1,%2,%3}, [%4];"
        : "=r"(r[0]), "=r"(r[1]), "=r"(r[2]), "=r"(r[3]) : "r"(addr));
}
__device__ __forceinline__ void mma16816(float* c, const uint32_t* a, uint32_t b0, uint32_t b1) {
    asm volatile("mma.sync.aligned.m16n8k16.row.col.f32.f16.f16.f32 "
        "{%0,%1,%2,%3}, {%4,%5,%6,%7}, {%8,%9}, {%0,%1,%2,%3};"
        : "+f"(c[0]), "+f"(c[1]), "+f"(c[2]), "+f"(c[3])
        : "r"(a[0]), "r"(a[1]), "r"(a[2]), "r"(a[3]), "r"(b0), "r"(b1));
}
#define CPA16(dst, src) \
    asm volatile("cp.async.cg.shared.global [%0], [%1], 16;" :: "r"(dst), "l"(src))
#define CPA_COMMIT() asm volatile("cp.async.commit_group;" ::: "memory")

// ---------------- phase 1a: triu(A) -> fp16 ----------------
__global__ __launch_bounds__(256) void p1_split_a(const float* __restrict__ A) {
    size_t e = ((size_t)blockIdx.x * 256 + threadIdx.x) * 4;
    int r = (int)(e >> 12);
    int k = (int)(e & 4095);
    float4 v = *reinterpret_cast<const float4*>(A + e);
    if (k + 0 < r) v.x = 0.f;
    if (k + 1 < r) v.y = 0.f;
    if (k + 2 < r) v.z = 0.f;
    if (k + 3 < r) v.w = 0.f;
    __half2* ph = reinterpret_cast<__half2*>(gAh + e);
    __half2 a, b;
    a.x = __float2half(v.x); a.y = __float2half(v.y);
    b.x = __float2half(v.z); b.y = __float2half(v.w);
    ph[0] = a; ph[1] = b;
}

// ---------------- phase 1b: transpose triu(B) -> fp16: gBt[c][k] = triu(B)[k][c] ----------------
__global__ __launch_bounds__(256) void p1_split_bt(const float* __restrict__ B) {
    __shared__ __half sh[32][33];
    int c0 = blockIdx.x * 32, k0 = blockIdx.y * 32;
    int tx = threadIdx.x, ty = threadIdx.y;  // (32, 8)
    #pragma unroll
    for (int j = 0; j < 4; j++) {
        int k = k0 + ty + 8 * j, c = c0 + tx;
        float v = (k <= c) ? B[(size_t)k * N4K + c] : 0.f;
        sh[ty + 8 * j][tx] = __float2half(v);
    }
    __syncthreads();
    #pragma unroll
    for (int j = 0; j < 4; j++) {
        int row = ty + 8 * j;
        gBth[(size_t)(c0 + row) * N4K + (k0 + tx)] = sh[tx][row];
    }
}

// ---------------- phase 2 ----------------
static constexpr int A_OFF = 0;        // 16KB (128 rows x 64k x 2B)
static constexpr int B_OFF = 16384;    // 32KB (256 rows x 64k x 2B)
static constexpr int STAGE = 49152;    // 48KB
static constexpr int NSTAGE = 4;
static constexpr int SMEM_TOTAL = NSTAGE * STAGE;   // 192KB
static constexpr int NUM_WINDOWS = 592;

__device__ __forceinline__ void load_chunk(char* smBase, int stage, int rowStart,
                                           int colStart, int k0, int tid) {
    uint32_t st = smem_u32(smBase) + stage * STAGE;
    #pragma unroll
    for (int t = 0; t < 4; t++) {
        int e = tid + (t << 8);
        int row = e >> 3, ch = e & 7;
        size_t src = (size_t)(rowStart + row) * N4K + k0 + ch * 8;
        uint32_t d = SWZ((uint32_t)(row * 128 + ch * 16));
        CPA16(st + A_OFF + d, gAh + src);
    }
    #pragma unroll
    for (int t = 0; t < 8; t++) {
        int e = tid + (t << 8);
        int row = e >> 3, ch = e & 7;
        size_t src = (size_t)(colStart + row) * N4K + k0 + ch * 8;
        uint32_t d = SWZ((uint32_t)(row * 128 + ch * 16));
        CPA16(st + B_OFF + d, gBth + src);
    }
    CPA_COMMIT();
}

__global__ __launch_bounds__(256, 1) void trimm_mma() {
    extern __shared__ char sm[];
    const int tid = threadIdx.x;
    const int wid = tid >> 5, lane = tid & 31;
    const int wm = wid & 3, wn = wid >> 2;     // 4 x 2 warp grid, warp tile 32x128

    // ---- decode bid -> (bx, by, kw); bx descending => biggest windows first ----
    int rem = blockIdx.x;
    int bx = 15;
    #pragma unroll 1
    for (; bx >= 0; --bx) {
        int T = 2 * bx + 2;
        int kh = bx >> 2;
        int W = 0;
        #pragma unroll
        for (int g = 0; g < 4; g++) {
            int cnt = T - 8 * g;
            cnt = cnt < 0 ? 0 : (cnt > 8 ? 8 : cnt);
            W += cnt * (kh + 1 - g);
        }
        if (rem < W) break;
        rem -= W;
    }
    const int kwHi = bx >> 2;
    int by = 0;
    #pragma unroll 1
    for (;; ++by) {
        int nw = kwHi - (by >> 3) + 1;
        if (rem < nw) break;
        rem -= nw;
    }
    const int kw = (by >> 3) + rem;

    const int rowStart = by * 128;
    const int colStart = bx * 256;
    int kstart = kw << 10;       if (kstart < rowStart)     kstart = rowStart;
    int kend   = (kw + 1) << 10; if (kend > colStart + 256) kend = colStart + 256;
    const int nCh = (kend - kstart) >> 6;   // 2..16

    float acc[128];
    #pragma unroll
    for (int i = 0; i < 128; i++) acc[i] = 0.f;

    // prefetch 3 stages (always commit 3 groups)
    load_chunk(sm, 0, rowStart, colStart, kstart, tid);
    load_chunk(sm, 1, rowStart, colStart, kstart + 64, tid);
    if (nCh > 2) load_chunk(sm, 2, rowStart, colStart, kstart + 128, tid);
    else         CPA_COMMIT();

    const int lrow = lane & 15;
    const int lk   = (lane >> 4) * 8;

    #pragma unroll 1
    for (int ci = 0; ci < nCh; ci++) {
        if (ci + 3 < nCh) load_chunk(sm, (ci + 3) & 3, rowStart, colStart,
                                     kstart + 64 * (ci + 3), tid);
        else              CPA_COMMIT();
        asm volatile("cp.async.wait_group 3;" ::: "memory");
        __syncthreads();

        const uint32_t st = smem_u32(sm) + (ci & 3) * STAGE;

        #pragma unroll
        for (int kk = 0; kk < 4; kk++) {
            const int krow = kk * 16;
            uint32_t a[2][4];
            #pragma unroll
            for (int i = 0; i < 2; i++) {
                uint32_t off = SWZ((uint32_t)((wm * 32 + i * 16 + lrow) * 128 + (krow + lk) * 2));
                ldmx4(a[i], st + A_OFF + off);
            }
            #pragma unroll
            for (int h = 0; h < 2; h++) {
                uint32_t b0[8], b1[8];
                #pragma unroll
                for (int j2 = 0; j2 < 4; j2++) {
                    uint32_t off = SWZ((uint32_t)((wn * 128 + h * 64 + j2 * 16 + lrow) * 128
                                                  + (krow + lk) * 2));
                    uint32_t r[4];
                    ldmx4(r, st + B_OFF + off);
                    b0[2 * j2] = r[0]; b1[2 * j2] = r[2];
                    b0[2 * j2 + 1] = r[1]; b1[2 * j2 + 1] = r[3];
                }
                #pragma unroll
                for (int i = 0; i < 2; i++) {
                    #pragma unroll
                    for (int j = 0; j < 8; j++) {
                        mma16816(&acc[(i * 16 + h * 8 + j) * 4], a[i], b0[j], b1[j]);
                    }
                }
            }
        }
        __syncthreads();
    }

    // ---- uniform epilogue: unmasked fp32 partial (tile-local 128x256) ----
    float* P = gPart + (((size_t)(bx * 32 + by) * 4 + kw) << 15);
    const int l4 = lane >> 2;
    const int l2 = (lane & 3) * 2;
    #pragma unroll
    for (int i = 0; i < 2; i++) {
        const int r0 = wm * 32 + i * 16 + l4;
        const int r1 = r0 + 8;
        #pragma unroll
        for (int j = 0; j < 16; j++) {
            const int c = wn * 128 + j * 8 + l2;
            const float* a = &acc[(i * 16 + j) * 4];
            float2 v;
            v.x = a[0]; v.y = a[1];
            *reinterpret_cast<float2*>(P + r0 * 256 + c) = v;
            v.x = a[2]; v.y = a[3];
            *reinterpret_cast<float2*>(P + r1 * 256 + c) = v;
        }
    }
}

// ---------------- phase 3: sum window partials, mask, store (covers ALL tiles) ----------------
__global__ __launch_bounds__(256) void reduce_tiles(float* __restrict__ C) {
    const int bx = blockIdx.x, by = blockIdx.y;
    const int sl = blockIdx.z;
    const int rowStart = by * 128, colStart = bx * 256;
    const int tid = threadIdx.x;

    if (by > 2 * bx + 1) {
        // strictly-lower tile: write zeros (replaces global memset)
        const float4 z = {0.f, 0.f, 0.f, 0.f};
        #pragma unroll
        for (int i = 0; i < 8; i++) {
            const int e = (i * 256 + tid) * 4;
            const int r = rowStart + sl * 32 + (e >> 8);
            const int c = colStart + (e & 255);
            *reinterpret_cast<float4*>(C + (size_t)r * N4K + c) = z;
        }
        return;
    }

    const int kwLo = by >> 3, kwHi = bx >> 2;
    const int nWin = kwHi - kwLo + 1;
    const float* P0 = gPart + (((size_t)(bx * 32 + by) * 4 + kwLo) << 15) + sl * 8192;

    float4 s[8];
    #pragma unroll
    for (int i = 0; i < 8; i++)
        s[i] = *reinterpret_cast<const float4*>(P0 + (size_t)(i * 256 + tid) * 4);
    const float* Pw = P0 + 32768;
    #pragma unroll 1
    for (int w = 1; w < nWin; w++, Pw += 32768) {
        #pragma unroll
        for (int i = 0; i < 8; i++) {
            float4 t = *reinterpret_cast<const float4*>(Pw + (size_t)(i * 256 + tid) * 4);
            s[i].x += t.x; s[i].y += t.y; s[i].z += t.z; s[i].w += t.w;
        }
    }
    #pragma unroll
    for (int i = 0; i < 8; i++) {
        const int e = (i * 256 + tid) * 4;
        const int r = rowStart + sl * 32 + (e >> 8);
        const int c = colStart + (e & 255);
        float4 v = s[i];
        if (r > c + 0) v.x = 0.f;
        if (r > c + 1) v.y = 0.f;
        if (r > c + 2) v.z = 0.f;
        if (r > c + 3) v.w = 0.f;
        *reinterpret_cast<float4*>(C + (size_t)r * N4K + c) = v;
    }
}

// ---------------- launch ----------------
extern "C" void kernel_launch(void* const* d_in, const int* in_sizes, int n_in,
                              void* d_out, int out_size) {
    const float* A = (const float*)d_in[0];
    const float* B = (const float*)d_in[1];
    float* C = (float*)d_out;

    p1_split_a<<<(N4K * (N4K / 4)) / 256, 256>>>(A);
    p1_split_bt<<<dim3(N4K / 32, N4K / 32), dim3(32, 8)>>>(B);

    cudaFuncSetAttribute(trimm_mma, cudaFuncAttributeMaxDynamicSharedMemorySize, SMEM_TOTAL);
    trimm_mma<<<NUM_WINDOWS, 256, SMEM_TOTAL>>>();

    reduce_tiles<<<dim3(16, 32, 4), 256>>>(C);
}

// round 8
// speedup vs baseline: 3.4940x; 1.0694x over previous
#include <cuda_runtime.h>
#include <cuda_fp16.h>
#include <cstdint>

// C = triu(triu(A) @ triu(B)), 4096x4096 fp32.
// Phase 1: A -> fp16 (masked triu), B -> fp16 transposed (masked); both skip
//          blocks the GEMM provably never reads (~47% traffic cut).
// Phase 2: fp16 mma.sync.m16n8k16, fp32 accum. SPLIT-K 1024-aligned windows,
//          4-stage cp.async pipeline. Uniform epilogue: masked store to C
//          (single-window tiles) or to gPart (multi-window), one code path.
// Phase 3: reducer: multi-window tiles summed in fixed order + masked;
//          strictly-lower tiles zero-filled; single-window tiles skipped.

#define N4K 4096

__device__ __align__(16) __half gAh[(size_t)N4K * N4K];
__device__ __align__(16) __half gBth[(size_t)N4K * N4K];
// partial buffer: slot = (bx*32+by)*4 + kw, each slot 128x256 fp32
__device__ __align__(16) float gPart[(size_t)2048 * 32768];

__device__ __forceinline__ uint32_t smem_u32(const void* p) {
    uint32_t a;
    asm("{ .reg .u64 t; cvta.to.shared.u64 t, %1; cvt.u32.u64 %0, t; }" : "=r"(a) : "l"(p));
    return a;
}
#define SWZ(x) ((x) ^ (((x) >> 3) & 0x70))

__device__ __forceinline__ void ldmx4(uint32_t* r, uint32_t addr) {
    asm volatile("ldmatrix.sync.aligned.m8n8.x4.shared.b16 {%0,%1,%2,%3}, [%4];"
        : "=r"(r[0]), "=r"(r[1]), "=r"(r[2]), "=r"(r[3]) : "r"(addr));
}
__device__ __forceinline__ void mma16816(float* c, const uint32_t* a, uint32_t b0, uint32_t b1) {
    asm volatile("mma.sync.aligned.m16n8k16.row.col.f32.f16.f16.f32 "
        "{%0,%1,%2,%3}, {%4,%5,%6,%7}, {%8,%9}, {%0,%1,%2,%3};"
        : "+f"(c[0]), "+f"(c[1]), "+f"(c[2]), "+f"(c[3])
        : "r"(a[0]), "r"(a[1]), "r"(a[2]), "r"(a[3]), "r"(b0), "r"(b1));
}
#define CPA16(dst, src) \
    asm volatile("cp.async.cg.shared.global [%0], [%1], 16;" :: "r"(dst), "l"(src))
#define CPA_COMMIT() asm volatile("cp.async.commit_group;" ::: "memory")

// ---------------- phase 1a: triu(A) -> fp16 (skip never-read chunks) ----------------
__global__ __launch_bounds__(256) void p1_split_a(const float* __restrict__ A) {
    const int bid = blockIdx.x;
    const int r  = bid >> 2;                 // row (1024 elems per CTA, 4 CTAs/row)
    const int k0 = (bid & 3) << 10;          // chunk start k
    // GEMM reads A[r][k] only for k >= (r & ~127): skip chunks fully below that.
    if (k0 + 1024 <= (r & ~127)) return;
    const int k = k0 + threadIdx.x * 4;
    const size_t e = (size_t)r * N4K + k;
    float4 v = *reinterpret_cast<const float4*>(A + e);
    if (k + 0 < r) v.x = 0.f;
    if (k + 1 < r) v.y = 0.f;
    if (k + 2 < r) v.z = 0.f;
    if (k + 3 < r) v.w = 0.f;
    __half2* ph = reinterpret_cast<__half2*>(gAh + e);
    __half2 a, b;
    a.x = __float2half(v.x); a.y = __float2half(v.y);
    b.x = __float2half(v.z); b.y = __float2half(v.w);
    ph[0] = a; ph[1] = b;
}

// ---------------- phase 1b: transpose triu(B) -> fp16 (skip never-read blocks) ----------------
__global__ __launch_bounds__(256) void p1_split_bt(const float* __restrict__ B) {
    __shared__ __half sh[32][33];
    const int c0 = blockIdx.x * 32, k0 = blockIdx.y * 32;
    // GEMM reads gBt[c][k] only for k < (c & ~255) + 256.
    if (k0 >= (c0 & ~255) + 256) return;
    const int tx = threadIdx.x, ty = threadIdx.y;  // (32, 8)
    if (k0 > c0 + 31) {
        // fully above diagonal: zeros, no B read
        #pragma unroll
        for (int j = 0; j < 4; j++) {
            int row = ty + 8 * j;
            gBth[(size_t)(c0 + row) * N4K + (k0 + tx)] = __float2half(0.f);
        }
        return;
    }
    #pragma unroll
    for (int j = 0; j < 4; j++) {
        int k = k0 + ty + 8 * j, c = c0 + tx;
        float v = (k <= c) ? B[(size_t)k * N4K + c] : 0.f;
        sh[ty + 8 * j][tx] = __float2half(v);
    }
    __syncthreads();
    #pragma unroll
    for (int j = 0; j < 4; j++) {
        int row = ty + 8 * j;
        gBth[(size_t)(c0 + row) * N4K + (k0 + tx)] = sh[tx][row];
    }
}

// ---------------- phase 2 ----------------
static constexpr int A_OFF = 0;        // 16KB (128 rows x 64k x 2B)
static constexpr int B_OFF = 16384;    // 32KB (256 rows x 64k x 2B)
static constexpr int STAGE = 49152;    // 48KB
static constexpr int NSTAGE = 4;
static constexpr int SMEM_TOTAL = NSTAGE * STAGE;   // 192KB
static constexpr int NUM_WINDOWS = 592;

__device__ __forceinline__ void load_chunk(char* smBase, int stage, int rowStart,
                                           int colStart, int k0, int tid) {
    uint32_t st = smem_u32(smBase) + stage * STAGE;
    #pragma unroll
    for (int t = 0; t < 4; t++) {
        int e = tid + (t << 8);
        int row = e >> 3, ch = e & 7;
        size_t src = (size_t)(rowStart + row) * N4K + k0 + ch * 8;
        uint32_t d = SWZ((uint32_t)(row * 128 + ch * 16));
        CPA16(st + A_OFF + d, gAh + src);
    }
    #pragma unroll
    for (int t = 0; t < 8; t++) {
        int e = tid + (t << 8);
        int row = e >> 3, ch = e & 7;
        size_t src = (size_t)(colStart + row) * N4K + k0 + ch * 8;
        uint32_t d = SWZ((uint32_t)(row * 128 + ch * 16));
        CPA16(st + B_OFF + d, gBth + src);
    }
    CPA_COMMIT();
}

__global__ __launch_bounds__(256, 1) void trimm_mma(float* __restrict__ C) {
    extern __shared__ char sm[];
    const int tid = threadIdx.x;
    const int wid = tid >> 5, lane = tid & 31;
    const int wm = wid & 3, wn = wid >> 2;     // 4 x 2 warp grid, warp tile 32x128

    // ---- decode bid -> (bx, by, kw); bx descending => biggest windows first ----
    int rem = blockIdx.x;
    int bx = 15;
    #pragma unroll 1
    for (; bx >= 0; --bx) {
        int T = 2 * bx + 2;
        int kh = bx >> 2;
        int W = 0;
        #pragma unroll
        for (int g = 0; g < 4; g++) {
            int cnt = T - 8 * g;
            cnt = cnt < 0 ? 0 : (cnt > 8 ? 8 : cnt);
            W += cnt * (kh + 1 - g);
        }
        if (rem < W) break;
        rem -= W;
    }
    const int kwHi = bx >> 2;
    int by = 0;
    #pragma unroll 1
    for (;; ++by) {
        int nw = kwHi - (by >> 3) + 1;
        if (rem < nw) break;
        rem -= nw;
    }
    const int kw = (by >> 3) + rem;
    const int nWin = kwHi - (by >> 3) + 1;

    const int rowStart = by * 128;
    const int colStart = bx * 256;
    int kstart = kw << 10;       if (kstart < rowStart)     kstart = rowStart;
    int kend   = (kw + 1) << 10; if (kend > colStart + 256) kend = colStart + 256;
    const int nCh = (kend - kstart) >> 6;   // 2..16

    float acc[128];
    #pragma unroll
    for (int i = 0; i < 128; i++) acc[i] = 0.f;

    // prefetch 3 stages (always commit 3 groups)
    load_chunk(sm, 0, rowStart, colStart, kstart, tid);
    load_chunk(sm, 1, rowStart, colStart, kstart + 64, tid);
    if (nCh > 2) load_chunk(sm, 2, rowStart, colStart, kstart + 128, tid);
    else         CPA_COMMIT();

    const int lrow = lane & 15;
    const int lk   = (lane >> 4) * 8;

    #pragma unroll 1
    for (int ci = 0; ci < nCh; ci++) {
        if (ci + 3 < nCh) load_chunk(sm, (ci + 3) & 3, rowStart, colStart,
                                     kstart + 64 * (ci + 3), tid);
        else              CPA_COMMIT();
        asm volatile("cp.async.wait_group 3;" ::: "memory");
        __syncthreads();

        const uint32_t st = smem_u32(sm) + (ci & 3) * STAGE;

        #pragma unroll
        for (int kk = 0; kk < 4; kk++) {
            const int krow = kk * 16;
            uint32_t a[2][4];
            #pragma unroll
            for (int i = 0; i < 2; i++) {
                uint32_t off = SWZ((uint32_t)((wm * 32 + i * 16 + lrow) * 128 + (krow + lk) * 2));
                ldmx4(a[i], st + A_OFF + off);
            }
            #pragma unroll
            for (int h = 0; h < 2; h++) {
                uint32_t b0[8], b1[8];
                #pragma unroll
                for (int j2 = 0; j2 < 4; j2++) {
                    uint32_t off = SWZ((uint32_t)((wn * 128 + h * 64 + j2 * 16 + lrow) * 128
                                                  + (krow + lk) * 2));
                    uint32_t r[4];
                    ldmx4(r, st + B_OFF + off);
                    b0[2 * j2] = r[0]; b1[2 * j2] = r[2];
                    b0[2 * j2 + 1] = r[1]; b1[2 * j2 + 1] = r[3];
                }
                #pragma unroll
                for (int i = 0; i < 2; i++) {
                    #pragma unroll
                    for (int j = 0; j < 8; j++) {
                        mma16816(&acc[(i * 16 + h * 8 + j) * 4], a[i], b0[j], b1[j]);
                    }
                }
            }
        }
        __syncthreads();
    }

    // ---- uniform epilogue: masked store; dst = C (single window) or gPart ----
    float* dst;
    int stride;
    if (nWin == 1) {
        dst = C + (size_t)rowStart * N4K + colStart;
        stride = N4K;
    } else {
        dst = gPart + (((size_t)(bx * 32 + by) * 4 + kw) << 15);
        stride = 256;
    }
    const int l4 = lane >> 2;
    const int l2 = (lane & 3) * 2;
    #pragma unroll
    for (int i = 0; i < 2; i++) {
        const int r0 = wm * 32 + i * 16 + l4;    // tile-local rows
        const int r1 = r0 + 8;
        const int g0 = rowStart + r0, g1 = rowStart + r1;
        #pragma unroll
        for (int j = 0; j < 16; j++) {
            const int c  = wn * 128 + j * 8 + l2; // tile-local col
            const int gc = colStart + c;
            const float* a = &acc[(i * 16 + j) * 4];
            float2 v;
            v.x = (g0 <= gc + 0) ? a[0] : 0.f;
            v.y = (g0 <= gc + 1) ? a[1] : 0.f;
            *reinterpret_cast<float2*>(dst + (size_t)r0 * stride + c) = v;
            v.x = (g1 <= gc + 0) ? a[2] : 0.f;
            v.y = (g1 <= gc + 1) ? a[3] : 0.f;
            *reinterpret_cast<float2*>(dst + (size_t)r1 * stride + c) = v;
        }
    }
}

// ---------------- phase 3: sum multi-window tiles; zero lower tiles ----------------
__global__ __launch_bounds__(256) void reduce_tiles(float* __restrict__ C) {
    const int bx = blockIdx.x, by = blockIdx.y;
    const int sl = blockIdx.z;
    const int rowStart = by * 128, colStart = bx * 256;
    const int tid = threadIdx.x;

    if (by > 2 * bx + 1) {
        // strictly-lower tile: zeros (replaces global memset)
        const float4 z = {0.f, 0.f, 0.f, 0.f};
        #pragma unroll
        for (int i = 0; i < 8; i++) {
            const int e = (i * 256 + tid) * 4;
            const int r = rowStart + sl * 32 + (e >> 8);
            const int c = colStart + (e & 255);
            *reinterpret_cast<float4*>(C + (size_t)r * N4K + c) = z;
        }
        return;
    }

    const int kwLo = by >> 3, kwHi = bx >> 2;
    const int nWin = kwHi - kwLo + 1;
    if (nWin == 1) return;   // GEMM stored this tile directly
    const float* P0 = gPart + (((size_t)(bx * 32 + by) * 4 + kwLo) << 15) + sl * 8192;

    float4 s[8];
    #pragma unroll
    for (int i = 0; i < 8; i++)
        s[i] = *reinterpret_cast<const float4*>(P0 + (size_t)(i * 256 + tid) * 4);
    const float* Pw = P0 + 32768;
    #pragma unroll 1
    for (int w = 1; w < nWin; w++, Pw += 32768) {
        #pragma unroll
        for (int i = 0; i < 8; i++) {
            float4 t = *reinterpret_cast<const float4*>(Pw + (size_t)(i * 256 + tid) * 4);
            s[i].x += t.x; s[i].y += t.y; s[i].z += t.z; s[i].w += t.w;
        }
    }
    #pragma unroll
    for (int i = 0; i < 8; i++) {
        const int e = (i * 256 + tid) * 4;
        const int r = rowStart + sl * 32 + (e >> 8);
        const int c = colStart + (e & 255);
        float4 v = s[i];
        if (r > c + 0) v.x = 0.f;
        if (r > c + 1) v.y = 0.f;
        if (r > c + 2) v.z = 0.f;
        if (r > c + 3) v.w = 0.f;
        *reinterpret_cast<float4*>(C + (size_t)r * N4K + c) = v;
    }
}

// ---------------- launch ----------------
extern "C" void kernel_launch(void* const* d_in, const int* in_sizes, int n_in,
                              void* d_out, int out_size) {
    const float* A = (const float*)d_in[0];
    const float* B = (const float*)d_in[1];
    float* C = (float*)d_out;

    p1_split_a<<<N4K * 4, 256>>>(A);
    p1_split_bt<<<dim3(N4K / 32, N4K / 32), dim3(32, 8)>>>(B);

    cudaFuncSetAttribute(trimm_mma, cudaFuncAttributeMaxDynamicSharedMemorySize, SMEM_TOTAL);
    trimm_mma<<<NUM_WINDOWS, 256, SMEM_TOTAL>>>(C);

    reduce_tiles<<<dim3(16, 32, 4), 256>>>(C);
}